// round 2
// baseline (speedup 1.0000x reference)
#include <cuda_runtime.h>
#include <math_constants.h>
#include <cstdint>

// Problem constants
#define BB 32
#define HH 12
#define LL 512
#define DD 768
#define HD 64
#define KSEL 255          // K = min(256, 512) - 1
#define KOUT 256          // K + 1

// Output layout: final_token [B,256,768] ++ final_mask [B,256] ++ tome_size [B,256]
#define OUT_MASK_OFF ((size_t)BB * KOUT * DD)
#define OUT_TOME_OFF (OUT_MASK_OFF + (size_t)BB * KOUT)

// ---------------- scratch (device globals; no allocation) ----------------
__device__ float g_imp[BB * LL];
__device__ float g_att[BB * LL];
__device__ int   g_idx[BB * KSEL];
__device__ float g_sent[BB * DD];
__device__ float g_q[BB * DD];
__device__ float g_kbias[BB * HH];
__device__ float g_wke[BB * HH * DD];
__device__ float g_w[BB * HH * LL];   // logits, then softmax weights (in place)
__device__ float g_hv[BB * HH * DD];
__device__ float g_ctx[BB * DD];

// ---------------- 0: zero importance accumulator ----------------
__global__ void k_zero_imp() {
    int i = blockIdx.x * blockDim.x + threadIdx.x;
    if (i < BB * LL) g_imp[i] = 0.f;
}

// ---------------- 1: column-sum of scores (the 402 MB pass) ----------------
// imp[b,l] += sum_{h, q in chunk} scores[b,h,q,l] * amf[b,q]
// grid = B*H*4 blocks (q-chunks of 128), 128 threads, float4 columns.
__global__ void k_reduce_scores(const float* __restrict__ scores,
                                const float* __restrict__ am) {
    const int t   = threadIdx.x;          // 0..127, covers 512 cols as float4
    const int blk = blockIdx.x;
    const int qc  = blk & 3;
    const int bh  = blk >> 2;
    const int h   = bh % HH;
    const int b   = bh / HH;

    __shared__ float s_af[128];
    const int q0 = qc * 128;
    if (t < 128) {
        float amv = am[b * LL + q0 + t];
        s_af[t] = (amv > -10.f) ? 1.f : 0.f;
    }
    __syncthreads();

    const float4* base =
        (const float4*)(scores + ((size_t)(b * HH + h) * LL + q0) * LL) + t;

    float4 acc = make_float4(0.f, 0.f, 0.f, 0.f);
#pragma unroll 4
    for (int q = 0; q < 128; q++) {
        float af = s_af[q];
        float4 v = base[(size_t)q * (LL / 4)];
        acc.x += af * v.x; acc.y += af * v.y;
        acc.z += af * v.z; acc.w += af * v.w;
    }
    float* dst = &g_imp[b * LL + t * 4];
    atomicAdd(dst + 0, acc.x);
    atomicAdd(dst + 1, acc.y);
    atomicAdd(dst + 2, acc.z);
    atomicAdd(dst + 3, acc.w);
}

// ---------------- 2: top-K selection + sentence softmax weights ----------------
// One block per batch, 512 threads.
__global__ void k_topk_att(const float* __restrict__ am) {
    const int t = threadIdx.x;        // 0..511
    const int b = blockIdx.x;

    __shared__ float sv[LL];
    __shared__ int   ssc[LL];
    __shared__ float red[LL];

    const float amv = am[b * LL + t];
    const float afl = (amv > -10.f) ? 1.f : 0.f;
    float v = g_imp[b * LL + t] * afl * (1.0f / (HH * LL));
    if (t == 0) v = CUDART_INF_F;
    sv[t] = v;
    __syncthreads();

    // exact stable rank (matches jax top_k tie-break: lower index wins)
    int rank = 0;
#pragma unroll 8
    for (int j = 0; j < LL; j++) {
        float vj = sv[j];
        rank += (vj > v) || (vj == v && j < t);
    }
    const int sel = (rank < KSEL) ? 1 : 0;

    // inclusive scan over index order -> sorted-index compaction
    ssc[t] = sel;
    __syncthreads();
    for (int off = 1; off < LL; off <<= 1) {
        int y = (t >= off) ? ssc[t - off] : 0;
        __syncthreads();
        ssc[t] += y;
        __syncthreads();
    }
    if (sel) g_idx[b * KSEL + (ssc[t] - 1)] = t;

    // att = softmax(am[b,:])  (plain, per reference)
    red[t] = amv;
    __syncthreads();
    for (int s = 256; s > 0; s >>= 1) {
        if (t < s) red[t] = fmaxf(red[t], red[t + s]);
        __syncthreads();
    }
    const float m = red[0];
    __syncthreads();
    const float e = __expf(amv - m);
    red[t] = e;
    __syncthreads();
    for (int s = 256; s > 0; s >>= 1) {
        if (t < s) red[t] += red[t + s];
        __syncthreads();
    }
    g_att[b * LL + t] = e / red[0];
}

// ---------------- 3: sentences[b,d] = sum_l att[b,l] * hidden[b,l,d] ----------------
// grid (6, B), 128 threads
__global__ void k_sentence(const float* __restrict__ hidden) {
    const int t  = threadIdx.x;
    const int dc = blockIdx.x;
    const int b  = blockIdx.y;
    __shared__ float s_att[LL];
    for (int i = t; i < LL; i += 128) s_att[i] = g_att[b * LL + i];
    __syncthreads();

    const float* hp = hidden + (size_t)b * LL * DD + dc * 128 + t;
    float acc = 0.f;
#pragma unroll 4
    for (int l = 0; l < LL; l++) acc += s_att[l] * hp[(size_t)l * DD];
    g_sent[b * DD + dc * 128 + t] = acc;
}

// ---------------- 4: q = sentences @ Wq + bq ----------------
__global__ void k_qproj(const float* __restrict__ Wq, const float* __restrict__ bq) {
    const int t  = threadIdx.x;
    const int dc = blockIdx.x;
    const int b  = blockIdx.y;
    __shared__ float s[DD];
    for (int i = t; i < DD; i += 128) s[i] = g_sent[b * DD + i];
    __syncthreads();
    const int d = dc * 128 + t;
    float acc = bq[d];
#pragma unroll 4
    for (int j = 0; j < DD; j++) acc += s[j] * Wq[(size_t)j * DD + d];
    g_q[b * DD + d] = acc;
}

// ---------------- 5: wke[b,h,j] = sum_d Wk[j, h*64+d] * q[b,h,d]; kbias ----------------
// grid (H, B), 256 threads
__global__ void k_wkeff(const float* __restrict__ Wk, const float* __restrict__ bk) {
    const int t = threadIdx.x;
    const int h = blockIdx.x;
    const int b = blockIdx.y;
    __shared__ float qh[HD];
    if (t < HD) qh[t] = g_q[b * DD + h * HD + t];
    __syncthreads();

    for (int j = t; j < DD; j += 256) {
        const float* wp = Wk + (size_t)j * DD + h * HD;
        float acc = 0.f;
#pragma unroll
        for (int d = 0; d < HD; d++) acc += wp[d] * qh[d];
        g_wke[((size_t)b * HH + h) * DD + j] = acc;
    }
    if (t == 0) {
        float kb = 0.f;
        for (int d = 0; d < HD; d++) kb += qh[d] * bk[h * HD + d];
        g_kbias[b * HH + h] = kb;
    }
}

// ---------------- 6: logits[b,h,l] = (hidden[b,l]·wke[b,h] + kbias)/8, pad->-inf ----------------
// grid (32 lchunks, B), 384 threads (12 warps = 12 heads)
__global__ void k_logits(const float* __restrict__ hidden, const float* __restrict__ am) {
    const int t = threadIdx.x;
    const int b = blockIdx.y;
    __shared__ float swk[HH * DD];   // 36 KB
    __shared__ float skb[HH];
    for (int i = t; i < HH * DD; i += 384) swk[i] = g_wke[(size_t)b * HH * DD + i];
    if (t < HH) skb[t] = g_kbias[b * HH + t];
    __syncthreads();

    const int w = t >> 5, lane = t & 31;
    for (int li = 0; li < 16; li++) {
        const int l = blockIdx.x * 16 + li;
        const float* hp = hidden + ((size_t)b * LL + l) * DD;
        float acc = 0.f;
#pragma unroll
        for (int i = lane; i < DD; i += 32) acc += hp[i] * swk[w * DD + i];
#pragma unroll
        for (int off = 16; off; off >>= 1) acc += __shfl_down_sync(0xffffffffu, acc, off);
        if (lane == 0) {
            const float amv = am[b * LL + l];
            g_w[((size_t)b * HH + w) * LL + l] =
                (amv < -10.f) ? -CUDART_INF_F : (acc + skb[w]) * 0.125f;
        }
    }
}

// ---------------- 7: softmax over l, in place. grid (B*H), 512 threads ----------------
__global__ void k_softmax_w() {
    const int t = threadIdx.x;
    const int bh = blockIdx.x;
    __shared__ float red[LL];
    const float v = g_w[(size_t)bh * LL + t];
    red[t] = v;
    __syncthreads();
    for (int s = 256; s > 0; s >>= 1) {
        if (t < s) red[t] = fmaxf(red[t], red[t + s]);
        __syncthreads();
    }
    const float m = red[0];
    __syncthreads();
    const float e = __expf(v - m);
    red[t] = e;
    __syncthreads();
    for (int s = 256; s > 0; s >>= 1) {
        if (t < s) red[t] += red[t + s];
        __syncthreads();
    }
    g_w[(size_t)bh * LL + t] = e / red[0];
}

// ---------------- 8: hv[b,h,d] = sum_l w[b,h,l] * hidden[b,l,d] ----------------
// grid (6, B), 128 threads, 12 accumulators
__global__ void k_hv(const float* __restrict__ hidden) {
    const int t  = threadIdx.x;
    const int dc = blockIdx.x;
    const int b  = blockIdx.y;
    __shared__ float sw[HH * LL];    // 24 KB
    for (int i = t; i < HH * LL; i += 128) sw[i] = g_w[(size_t)b * HH * LL + i];
    __syncthreads();

    float acc[HH];
#pragma unroll
    for (int h = 0; h < HH; h++) acc[h] = 0.f;

    const float* hp = hidden + (size_t)b * LL * DD + dc * 128 + t;
#pragma unroll 2
    for (int l = 0; l < LL; l++) {
        const float hval = hp[(size_t)l * DD];
#pragma unroll
        for (int h = 0; h < HH; h++) acc[h] += sw[h * LL + l] * hval;
    }
#pragma unroll
    for (int h = 0; h < HH; h++)
        g_hv[((size_t)b * HH + h) * DD + dc * 128 + t] = acc[h];
}

// ---------------- 9: ctx[b, h*64+d] = hv[b,h]·Wv[:,h*64+d] + bv ----------------
// grid (H, B), 64 threads
__global__ void k_ctx(const float* __restrict__ Wv, const float* __restrict__ bv) {
    const int t = threadIdx.x;   // = d within head
    const int h = blockIdx.x;
    const int b = blockIdx.y;
    __shared__ float sh[DD];
    for (int i = t; i < DD; i += 64) sh[i] = g_hv[((size_t)b * HH + h) * DD + i];
    __syncthreads();
    float acc = bv[h * HD + t];
#pragma unroll 4
    for (int j = 0; j < DD; j++) acc += sh[j] * Wv[(size_t)j * DD + h * HD + t];
    g_ctx[b * DD + h * HD + t] = acc;
}

// ---------------- 10: new_token = ctx @ Wo + bo, write row 255 ----------------
// grid (6, B), 128 threads
__global__ void k_newtok(const float* __restrict__ Wo, const float* __restrict__ bo,
                         float* __restrict__ out) {
    const int t  = threadIdx.x;
    const int dc = blockIdx.x;
    const int b  = blockIdx.y;
    __shared__ float sc[DD];
    for (int i = t; i < DD; i += 128) sc[i] = g_ctx[b * DD + i];
    __syncthreads();
    const int d = dc * 128 + t;
    float acc = bo[d];
#pragma unroll 4
    for (int j = 0; j < DD; j++) acc += sc[j] * Wo[(size_t)j * DD + d];
    out[((size_t)b * KOUT + KSEL) * DD + d] = acc;
    if (dc == 0 && t == 0) {
        out[OUT_MASK_OFF + (size_t)b * KOUT + KSEL] = 0.f;  // new token mask
        out[OUT_TOME_OFF + (size_t)b * KOUT + KSEL] = 1.f;
    }
}

// ---------------- 11: gather preserved rows + mask + tome ----------------
// grid (KSEL, B), 192 threads (float4)
__global__ void k_gather(const float* __restrict__ hidden, const float* __restrict__ am,
                         float* __restrict__ out) {
    const int t = threadIdx.x;
    const int k = blockIdx.x;
    const int b = blockIdx.y;
    const int idx = g_idx[b * KSEL + k];
    const float4* src = (const float4*)(hidden + ((size_t)b * LL + idx) * DD);
    float4* dst = (float4*)(out + ((size_t)b * KOUT + k) * DD);
    dst[t] = src[t];
    if (t == 0) {
        out[OUT_MASK_OFF + (size_t)b * KOUT + k] = am[b * LL + idx];
        out[OUT_TOME_OFF + (size_t)b * KOUT + k] = 1.f;
    }
}

// ---------------- launcher ----------------
extern "C" void kernel_launch(void* const* d_in, const int* in_sizes, int n_in,
                              void* d_out, int out_size) {
    const float* hidden = (const float*)d_in[0];
    const float* am     = (const float*)d_in[1];
    const float* scores = (const float*)d_in[2];
    const float* Wq     = (const float*)d_in[3];
    const float* bq     = (const float*)d_in[4];
    const float* Wk     = (const float*)d_in[5];
    const float* bk     = (const float*)d_in[6];
    const float* Wv     = (const float*)d_in[7];
    const float* bv     = (const float*)d_in[8];
    const float* Wo     = (const float*)d_in[9];
    const float* bo     = (const float*)d_in[10];
    float* out = (float*)d_out;

    k_zero_imp<<<(BB * LL + 511) / 512, 512>>>();
    k_reduce_scores<<<BB * HH * 4, 128>>>(scores, am);
    k_topk_att<<<BB, LL>>>(am);
    {
        dim3 g(6, BB);
        k_sentence<<<g, 128>>>(hidden);
        k_qproj<<<g, 128>>>(Wq, bq);
    }
    {
        dim3 g(HH, BB);
        k_wkeff<<<g, 256>>>(Wk, bk);
    }
    {
        dim3 g(32, BB);
        k_logits<<<g, 384>>>(hidden, am);
    }
    k_softmax_w<<<BB * HH, LL>>>();
    {
        dim3 g(6, BB);
        k_hv<<<g, 128>>>(hidden);
    }
    {
        dim3 g(HH, BB);
        k_ctx<<<g, 64>>>(Wv, bv);
    }
    {
        dim3 g(6, BB);
        k_newtok<<<g, 128>>>(Wo, bo, out);
    }
    {
        dim3 g(KSEL, BB);
        k_gather<<<g, 192>>>(hidden, am, out);
    }
}

// round 4
// speedup vs baseline: 1.1850x; 1.1850x over previous
#include <cuda_runtime.h>
#include <math_constants.h>
#include <cstdint>

// Problem constants
#define BB 32
#define HH 12
#define LL 512
#define DD 768
#define HD 64
#define KSEL 255          // K = min(256, 512) - 1
#define KOUT 256          // K + 1

// Output layout: final_token [B,256,768] ++ final_mask [B,256] ++ tome_size [B,256]
#define OUT_MASK_OFF ((size_t)BB * KOUT * DD)
#define OUT_TOME_OFF (OUT_MASK_OFF + (size_t)BB * KOUT)

// ---------------- scratch (device globals; no allocation) ----------------
__device__ float g_imp[BB * LL];
__device__ float g_att[BB * LL];
__device__ int   g_idx[BB * KSEL];
__device__ float g_sent[BB * DD];
__device__ float g_q[BB * DD];
__device__ float g_kbias[BB * HH];
__device__ float g_wke[BB * HH * DD];
__device__ float g_w[BB * HH * LL];   // logits, then softmax weights (in place)
__device__ float g_hv[BB * HH * DD];
__device__ float g_ctx[BB * DD];

// ---------------- 0: zero accumulators (imp, sent, hv) ----------------
__global__ void k_zero() {
    const int i = blockIdx.x * blockDim.x + threadIdx.x;
    if (i < BB * LL) g_imp[i] = 0.f;
    if (i < BB * DD) g_sent[i] = 0.f;
    if (i < BB * HH * DD) g_hv[i] = 0.f;
}

// ---------------- 1: column-sum of scores (the 402 MB pass) ----------------
// imp[b,l] += sum_{h, q in chunk} scores[b,h,q,l] * amf[b,q]
// grid = B*H*4 blocks (q-chunks of 128), 128 threads, float4 columns.
__global__ void k_reduce_scores(const float* __restrict__ scores,
                                const float* __restrict__ am) {
    const int t   = threadIdx.x;          // 0..127, covers 512 cols as float4
    const int blk = blockIdx.x;
    const int qc  = blk & 3;
    const int bh  = blk >> 2;
    const int h   = bh % HH;
    const int b   = bh / HH;

    __shared__ float s_af[128];
    const int q0 = qc * 128;
    {
        float amv = am[b * LL + q0 + t];
        s_af[t] = (amv > -10.f) ? 1.f : 0.f;
    }
    __syncthreads();

    const float4* base =
        (const float4*)(scores + ((size_t)(b * HH + h) * LL + q0) * LL) + t;

    float4 acc = make_float4(0.f, 0.f, 0.f, 0.f);
#pragma unroll 8
    for (int q = 0; q < 128; q++) {
        float af = s_af[q];
        float4 v = base[(size_t)q * (LL / 4)];
        acc.x += af * v.x; acc.y += af * v.y;
        acc.z += af * v.z; acc.w += af * v.w;
    }
    float* dst = &g_imp[b * LL + t * 4];
    atomicAdd(dst + 0, acc.x);
    atomicAdd(dst + 1, acc.y);
    atomicAdd(dst + 2, acc.z);
    atomicAdd(dst + 3, acc.w);
}

// ---------------- 2: top-K selection + sentence softmax weights ----------------
// One block per batch, 512 threads.
__global__ void k_topk_att(const float* __restrict__ am) {
    const int t = threadIdx.x;        // 0..511
    const int b = blockIdx.x;

    __shared__ float sv[LL];
    __shared__ int   ssc[LL];
    __shared__ float red[LL];

    const float amv = am[b * LL + t];
    const float afl = (amv > -10.f) ? 1.f : 0.f;
    float v = g_imp[b * LL + t] * afl * (1.0f / (HH * LL));
    if (t == 0) v = CUDART_INF_F;
    sv[t] = v;
    __syncthreads();

    // exact stable rank (matches jax top_k tie-break: lower index wins)
    int rank = 0;
#pragma unroll 8
    for (int j = 0; j < LL; j++) {
        float vj = sv[j];
        rank += (vj > v) || (vj == v && j < t);
    }
    const int sel = (rank < KSEL) ? 1 : 0;

    // inclusive scan over index order -> sorted-index compaction
    ssc[t] = sel;
    __syncthreads();
    for (int off = 1; off < LL; off <<= 1) {
        int y = (t >= off) ? ssc[t - off] : 0;
        __syncthreads();
        ssc[t] += y;
        __syncthreads();
    }
    if (sel) g_idx[b * KSEL + (ssc[t] - 1)] = t;

    // att = softmax(am[b,:])  (plain, per reference)
    red[t] = amv;
    __syncthreads();
    for (int s = 256; s > 0; s >>= 1) {
        if (t < s) red[t] = fmaxf(red[t], red[t + s]);
        __syncthreads();
    }
    const float m = red[0];
    __syncthreads();
    const float e = __expf(amv - m);
    red[t] = e;
    __syncthreads();
    for (int s = 256; s > 0; s >>= 1) {
        if (t < s) red[t] += red[t + s];
        __syncthreads();
    }
    g_att[b * LL + t] = e / red[0];
}

// ---------------- 3: sentences[b,d] += sum_{l in chunk} att[b,l]*hidden[b,l,d] ----
// grid (6 dchunks, 4 lchunks, B), 128 threads
__global__ void k_sentence(const float* __restrict__ hidden) {
    const int t  = threadIdx.x;
    const int dc = blockIdx.x;
    const int lc = blockIdx.y;
    const int b  = blockIdx.z;
    __shared__ float s_att[128];
    s_att[t] = g_att[b * LL + lc * 128 + t];
    __syncthreads();

    const float* hp = hidden + ((size_t)b * LL + lc * 128) * DD + dc * 128 + t;
    float acc = 0.f;
#pragma unroll 8
    for (int l = 0; l < 128; l++) acc += s_att[l] * hp[(size_t)l * DD];
    atomicAdd(&g_sent[b * DD + dc * 128 + t], acc);
}

// ---------------- 4: q = sentences @ Wq + bq ----------------
__global__ void k_qproj(const float* __restrict__ Wq, const float* __restrict__ bq) {
    const int t  = threadIdx.x;
    const int dc = blockIdx.x;
    const int b  = blockIdx.y;
    __shared__ float s[DD];
    for (int i = t; i < DD; i += 128) s[i] = g_sent[b * DD + i];
    __syncthreads();
    const int d = dc * 128 + t;
    float acc = bq[d];
#pragma unroll 4
    for (int j = 0; j < DD; j++) acc += s[j] * Wq[(size_t)j * DD + d];
    g_q[b * DD + d] = acc;
}

// ---------------- 5: wke[b,h,j] = sum_d Wk[j, h*64+d] * q[b,h,d]; kbias ----------------
// grid (H, B), 256 threads
__global__ void k_wkeff(const float* __restrict__ Wk, const float* __restrict__ bk) {
    const int t = threadIdx.x;
    const int h = blockIdx.x;
    const int b = blockIdx.y;
    __shared__ float qh[HD];
    if (t < HD) qh[t] = g_q[b * DD + h * HD + t];
    __syncthreads();

    for (int j = t; j < DD; j += 256) {
        const float* wp = Wk + (size_t)j * DD + h * HD;
        float acc = 0.f;
#pragma unroll
        for (int d = 0; d < HD; d++) acc += wp[d] * qh[d];
        g_wke[((size_t)b * HH + h) * DD + j] = acc;
    }
    if (t == 0) {
        float kb = 0.f;
        for (int d = 0; d < HD; d++) kb += qh[d] * bk[h * HD + d];
        g_kbias[b * HH + h] = kb;
    }
}

// ---------------- 6: logits[b,h,l] = (hidden[b,l]·wke[b,h] + kbias)/8, pad->-inf ----
// grid (32 lchunks, B), 384 threads (12 warps = 12 heads)
__global__ void k_logits(const float* __restrict__ hidden, const float* __restrict__ am) {
    const int t = threadIdx.x;
    const int b = blockIdx.y;
    __shared__ float swk[HH * DD];   // 36 KB
    __shared__ float skb[HH];
    for (int i = t; i < HH * DD; i += 384) swk[i] = g_wke[(size_t)b * HH * DD + i];
    if (t < HH) skb[t] = g_kbias[b * HH + t];
    __syncthreads();

    const int w = t >> 5, lane = t & 31;
    for (int li = 0; li < 16; li++) {
        const int l = blockIdx.x * 16 + li;
        const float* hp = hidden + ((size_t)b * LL + l) * DD;
        float acc = 0.f;
#pragma unroll
        for (int i = lane; i < DD; i += 32) acc += hp[i] * swk[w * DD + i];
#pragma unroll
        for (int off = 16; off; off >>= 1) acc += __shfl_down_sync(0xffffffffu, acc, off);
        if (lane == 0) {
            const float amv = am[b * LL + l];
            g_w[((size_t)b * HH + w) * LL + l] =
                (amv < -10.f) ? -CUDART_INF_F : (acc + skb[w]) * 0.125f;
        }
    }
}

// ---------------- 7: softmax over l, in place. grid (B*H), 512 threads ----------------
__global__ void k_softmax_w() {
    const int t = threadIdx.x;
    const int bh = blockIdx.x;
    __shared__ float red[LL];
    const float v = g_w[(size_t)bh * LL + t];
    red[t] = v;
    __syncthreads();
    for (int s = 256; s > 0; s >>= 1) {
        if (t < s) red[t] = fmaxf(red[t], red[t + s]);
        __syncthreads();
    }
    const float m = red[0];
    __syncthreads();
    const float e = __expf(v - m);
    red[t] = e;
    __syncthreads();
    for (int s = 256; s > 0; s >>= 1) {
        if (t < s) red[t] += red[t + s];
        __syncthreads();
    }
    g_w[(size_t)bh * LL + t] = e / red[0];
}

// ---------------- 8: hv[b,h,d] += sum_{l in chunk} w[b,h,l]*hidden[b,l,d] ----------
// grid (6 dchunks, 4 lchunks, B), 128 threads, 12 accumulators
__global__ void k_hv(const float* __restrict__ hidden) {
    const int t  = threadIdx.x;
    const int dc = blockIdx.x;
    const int lc = blockIdx.y;
    const int b  = blockIdx.z;
    __shared__ float sw[HH * 128];   // 6 KB
    for (int i = t; i < HH * 128; i += 128) {
        const int h = i >> 7, l = i & 127;
        sw[i] = g_w[((size_t)b * HH + h) * LL + lc * 128 + l];
    }
    __syncthreads();

    float acc[HH];
#pragma unroll
    for (int h = 0; h < HH; h++) acc[h] = 0.f;

    const float* hp = hidden + ((size_t)b * LL + lc * 128) * DD + dc * 128 + t;
#pragma unroll 4
    for (int l = 0; l < 128; l++) {
        const float hval = hp[(size_t)l * DD];
#pragma unroll
        for (int h = 0; h < HH; h++) acc[h] += sw[h * 128 + l] * hval;
    }
#pragma unroll
    for (int h = 0; h < HH; h++)
        atomicAdd(&g_hv[((size_t)b * HH + h) * DD + dc * 128 + t], acc[h]);
}

// ---------------- 9: ctx[b, h*64+d] = hv[b,h]·Wv[:,h*64+d] + bv ----------------
// grid (H, B), 64 threads
__global__ void k_ctx(const float* __restrict__ Wv, const float* __restrict__ bv) {
    const int t = threadIdx.x;   // = d within head
    const int h = blockIdx.x;
    const int b = blockIdx.y;
    __shared__ float sh[DD];
    for (int i = t; i < DD; i += 64) sh[i] = g_hv[((size_t)b * HH + h) * DD + i];
    __syncthreads();
    float acc = bv[h * HD + t];
#pragma unroll 4
    for (int j = 0; j < DD; j++) acc += sh[j] * Wv[(size_t)j * DD + h * HD + t];
    g_ctx[b * DD + h * HD + t] = acc;
}

// ---------------- 10: new_token = ctx @ Wo + bo, write row 255 ----------------
// grid (6, B), 128 threads
__global__ void k_newtok(const float* __restrict__ Wo, const float* __restrict__ bo,
                         float* __restrict__ out) {
    const int t  = threadIdx.x;
    const int dc = blockIdx.x;
    const int b  = blockIdx.y;
    __shared__ float sc[DD];
    for (int i = t; i < DD; i += 128) sc[i] = g_ctx[b * DD + i];
    __syncthreads();
    const int d = dc * 128 + t;
    float acc = bo[d];
#pragma unroll 4
    for (int j = 0; j < DD; j++) acc += sc[j] * Wo[(size_t)j * DD + d];
    out[((size_t)b * KOUT + KSEL) * DD + d] = acc;
    if (dc == 0 && t == 0) {
        out[OUT_MASK_OFF + (size_t)b * KOUT + KSEL] = 0.f;  // new token mask
        out[OUT_TOME_OFF + (size_t)b * KOUT + KSEL] = 1.f;
    }
}

// ---------------- 11: gather preserved rows + mask + tome ----------------
// grid (KSEL, B), 192 threads (float4)
__global__ void k_gather(const float* __restrict__ hidden, const float* __restrict__ am,
                         float* __restrict__ out) {
    const int t = threadIdx.x;
    const int k = blockIdx.x;
    const int b = blockIdx.y;
    const int idx = g_idx[b * KSEL + k];
    const float4* src = (const float4*)(hidden + ((size_t)b * LL + idx) * DD);
    float4* dst = (float4*)(out + ((size_t)b * KOUT + k) * DD);
    dst[t] = src[t];
    if (t == 0) {
        out[OUT_MASK_OFF + (size_t)b * KOUT + k] = am[b * LL + idx];
        out[OUT_TOME_OFF + (size_t)b * KOUT + k] = 1.f;
    }
}

// ---------------- launcher ----------------
extern "C" void kernel_launch(void* const* d_in, const int* in_sizes, int n_in,
                              void* d_out, int out_size) {
    const float* hidden = (const float*)d_in[0];
    const float* am     = (const float*)d_in[1];
    const float* scores = (const float*)d_in[2];
    const float* Wq     = (const float*)d_in[3];
    const float* bq     = (const float*)d_in[4];
    const float* Wk     = (const float*)d_in[5];
    const float* bk     = (const float*)d_in[6];
    const float* Wv     = (const float*)d_in[7];
    const float* bv     = (const float*)d_in[8];
    const float* Wo     = (const float*)d_in[9];
    const float* bo     = (const float*)d_in[10];
    float* out = (float*)d_out;

    k_zero<<<(BB * HH * DD + 511) / 512, 512>>>();
    k_reduce_scores<<<BB * HH * 4, 128>>>(scores, am);
    k_topk_att<<<BB, LL>>>(am);
    {
        dim3 g(6, 4, BB);
        k_sentence<<<g, 128>>>(hidden);
    }
    {
        dim3 g(6, BB);
        k_qproj<<<g, 128>>>(Wq, bq);
    }
    {
        dim3 g(HH, BB);
        k_wkeff<<<g, 256>>>(Wk, bk);
    }
    {
        dim3 g(32, BB);
        k_logits<<<g, 384>>>(hidden, am);
    }
    k_softmax_w<<<BB * HH, LL>>>();
    {
        dim3 g(6, 4, BB);
        k_hv<<<g, 128>>>(hidden);
    }
    {
        dim3 g(HH, BB);
        k_ctx<<<g, 64>>>(Wv, bv);
    }
    {
        dim3 g(6, BB);
        k_newtok<<<g, 128>>>(Wo, bo, out);
    }
    {
        dim3 g(KSEL, BB);
        k_gather<<<g, 192>>>(hidden, am, out);
    }
}

// round 5
// speedup vs baseline: 1.2055x; 1.0174x over previous
#include <cuda_runtime.h>
#include <math_constants.h>
#include <cstdint>

// Problem constants
#define BB 32
#define HH 12
#define LL 512
#define DD 768
#define HD 64
#define KSEL 255          // K = min(256, 512) - 1
#define KOUT 256          // K + 1

// Output layout: final_token [B,256,768] ++ final_mask [B,256] ++ tome_size [B,256]
#define OUT_MASK_OFF ((size_t)BB * KOUT * DD)
#define OUT_TOME_OFF (OUT_MASK_OFF + (size_t)BB * KOUT)

// ---------------- scratch (device globals; no allocation) ----------------
__device__ float g_imp[BB * LL];
__device__ float g_att[BB * LL];
__device__ int   g_idx[BB * KSEL];
__device__ float g_sent[BB * DD];
__device__ float g_q[BB * DD];
__device__ float g_kbias[BB * HH];
__device__ float g_wke[BB * HH * DD];
__device__ float g_w[BB * HH * LL];   // logits, then softmax weights (in place)
__device__ float g_hv[BB * HH * DD];
__device__ float g_ctx[BB * DD];

// ---------------- 1: zero accumulators (imp, sent, hv) ----------------
__global__ void k_zero() {
    const int i = blockIdx.x * blockDim.x + threadIdx.x;
    if (i < BB * LL) g_imp[i] = 0.f;
    if (i < BB * DD) g_sent[i] = 0.f;
    if (i < BB * HH * DD) g_hv[i] = 0.f;
}

// ---------------- 2: constant outputs (tome_size = 1, new-token mask = 0) ----
__global__ void k_tome_init(float* __restrict__ out) {
    const int i = blockIdx.x * blockDim.x + threadIdx.x;
    if (i < BB * KOUT) out[OUT_TOME_OFF + i] = 1.f;
    if (i < BB) out[OUT_MASK_OFF + (size_t)i * KOUT + KSEL] = 0.f;
}

// ---------------- 3: att = softmax(am) per batch (independent of scores) ----
__global__ void k_att(const float* __restrict__ am) {
    const int t = threadIdx.x;        // 0..511
    const int b = blockIdx.x;
    __shared__ float red[LL];
    const float amv = am[b * LL + t];
    red[t] = amv;
    __syncthreads();
    for (int s = 256; s > 0; s >>= 1) {
        if (t < s) red[t] = fmaxf(red[t], red[t + s]);
        __syncthreads();
    }
    const float m = red[0];
    __syncthreads();
    const float e = __expf(amv - m);
    red[t] = e;
    __syncthreads();
    for (int s = 256; s > 0; s >>= 1) {
        if (t < s) red[t] += red[t + s];
        __syncthreads();
    }
    g_att[b * LL + t] = e / red[0];
}

// ---------------- 4: column-sum of scores (the 402 MB pass) [PROFILED SLOT] --
// imp[b,l] += sum_{h, q in chunk} scores[b,h,q,l] * amf[b,q]
// grid = B*H*2 blocks (q-chunks of 256), 128 threads, float4 columns.
// Two independent row-streams per thread; unroll 4 -> 8 loads in flight.
// __ldcs: streaming (evict-first) so hidden stays L2-resident for later passes.
__global__ void k_reduce_scores(const float* __restrict__ scores,
                                const float* __restrict__ am) {
    const int t   = threadIdx.x;          // 0..127, covers 512 cols as float4
    const int blk = blockIdx.x;
    const int qc  = blk & 1;
    const int bh  = blk >> 1;
    const int b   = bh / HH;

    __shared__ float s_af[256];
    const int q0 = qc * 256;
#pragma unroll
    for (int i = t; i < 256; i += 128) {
        float amv = am[b * LL + q0 + i];
        s_af[i] = (amv > -10.f) ? 1.f : 0.f;
    }
    __syncthreads();

    const float4* base =
        (const float4*)(scores + ((size_t)bh * LL + q0) * LL) + t;

    float4 a0 = make_float4(0.f, 0.f, 0.f, 0.f);
    float4 a1 = make_float4(0.f, 0.f, 0.f, 0.f);
#pragma unroll 4
    for (int q = 0; q < 128; q++) {
        const float af0 = s_af[q];
        const float af1 = s_af[q + 128];
        float4 v0 = __ldcs(base + (size_t)q * (LL / 4));
        float4 v1 = __ldcs(base + (size_t)(q + 128) * (LL / 4));
        a0.x += af0 * v0.x; a0.y += af0 * v0.y;
        a0.z += af0 * v0.z; a0.w += af0 * v0.w;
        a1.x += af1 * v1.x; a1.y += af1 * v1.y;
        a1.z += af1 * v1.z; a1.w += af1 * v1.w;
    }
    float* dst = &g_imp[b * LL + t * 4];
    atomicAdd(dst + 0, a0.x + a1.x);
    atomicAdd(dst + 1, a0.y + a1.y);
    atomicAdd(dst + 2, a0.z + a1.z);
    atomicAdd(dst + 3, a0.w + a1.w);
}

// ---------------- 5: top-K selection (exact stable rank + scan) ----------------
__global__ void k_topk(const float* __restrict__ am) {
    const int t = threadIdx.x;        // 0..511
    const int b = blockIdx.x;

    __shared__ float sv[LL];
    __shared__ int   ssc[LL];

    const float amv = am[b * LL + t];
    const float afl = (amv > -10.f) ? 1.f : 0.f;
    float v = g_imp[b * LL + t] * afl * (1.0f / (HH * LL));
    if (t == 0) v = CUDART_INF_F;
    sv[t] = v;
    __syncthreads();

    // exact stable rank (matches jax top_k tie-break: lower index wins)
    int rank = 0;
#pragma unroll 8
    for (int j = 0; j < LL; j++) {
        float vj = sv[j];
        rank += (vj > v) || (vj == v && j < t);
    }
    const int sel = (rank < KSEL) ? 1 : 0;

    // inclusive scan over index order -> sorted-index compaction
    ssc[t] = sel;
    __syncthreads();
    for (int off = 1; off < LL; off <<= 1) {
        int y = (t >= off) ? ssc[t - off] : 0;
        __syncthreads();
        ssc[t] += y;
        __syncthreads();
    }
    if (sel) g_idx[b * KSEL + (ssc[t] - 1)] = t;
}

// ---------------- 6: sentences[b,d] += sum_{l in chunk} att[b,l]*hidden[b,l,d] ----
// grid (6 dchunks, 8 lchunks, B), 128 threads, chunk of 64 l's
__global__ void k_sentence(const float* __restrict__ hidden) {
    const int t  = threadIdx.x;
    const int dc = blockIdx.x;
    const int lc = blockIdx.y;
    const int b  = blockIdx.z;
    __shared__ float s_att[64];
    if (t < 64) s_att[t] = g_att[b * LL + lc * 64 + t];
    __syncthreads();

    const float* hp = hidden + ((size_t)b * LL + lc * 64) * DD + dc * 128 + t;
    float acc = 0.f;
#pragma unroll 16
    for (int l = 0; l < 64; l++) acc += s_att[l] * hp[(size_t)l * DD];
    atomicAdd(&g_sent[b * DD + dc * 128 + t], acc);
}

// ---------------- 7: q = sentences @ Wq + bq ----------------
__global__ void k_qproj(const float* __restrict__ Wq, const float* __restrict__ bq) {
    const int t  = threadIdx.x;
    const int dc = blockIdx.x;
    const int b  = blockIdx.y;
    __shared__ float s[DD];
    for (int i = t; i < DD; i += 128) s[i] = g_sent[b * DD + i];
    __syncthreads();
    const int d = dc * 128 + t;
    float acc = bq[d];
#pragma unroll 4
    for (int j = 0; j < DD; j++) acc += s[j] * Wq[(size_t)j * DD + d];
    g_q[b * DD + d] = acc;
}

// ---------------- 8: wke[b,h,j] = sum_d Wk[j, h*64+d] * q[b,h,d]; kbias ----------------
// grid (H, B), 256 threads
__global__ void k_wkeff(const float* __restrict__ Wk, const float* __restrict__ bk) {
    const int t = threadIdx.x;
    const int h = blockIdx.x;
    const int b = blockIdx.y;
    __shared__ float qh[HD];
    if (t < HD) qh[t] = g_q[b * DD + h * HD + t];
    __syncthreads();

    for (int j = t; j < DD; j += 256) {
        const float* wp = Wk + (size_t)j * DD + h * HD;
        float acc = 0.f;
#pragma unroll
        for (int d = 0; d < HD; d++) acc += wp[d] * qh[d];
        g_wke[((size_t)b * HH + h) * DD + j] = acc;
    }
    if (t == 0) {
        float kb = 0.f;
        for (int d = 0; d < HD; d++) kb += qh[d] * bk[h * HD + d];
        g_kbias[b * HH + h] = kb;
    }
}

// ---------------- 9: logits[b,h,l] = (hidden[b,l]·wke[b,h] + kbias)/8, pad->-inf ----
// grid (32 lchunks, B), 384 threads (12 warps = 12 heads)
__global__ void k_logits(const float* __restrict__ hidden, const float* __restrict__ am) {
    const int t = threadIdx.x;
    const int b = blockIdx.y;
    __shared__ float swk[HH * DD];   // 36 KB
    __shared__ float skb[HH];
    for (int i = t; i < HH * DD; i += 384) swk[i] = g_wke[(size_t)b * HH * DD + i];
    if (t < HH) skb[t] = g_kbias[b * HH + t];
    __syncthreads();

    const int w = t >> 5, lane = t & 31;
    for (int li = 0; li < 16; li++) {
        const int l = blockIdx.x * 16 + li;
        const float* hp = hidden + ((size_t)b * LL + l) * DD;
        float acc = 0.f;
#pragma unroll
        for (int i = lane; i < DD; i += 32) acc += hp[i] * swk[w * DD + i];
#pragma unroll
        for (int off = 16; off; off >>= 1) acc += __shfl_down_sync(0xffffffffu, acc, off);
        if (lane == 0) {
            const float amv = am[b * LL + l];
            g_w[((size_t)b * HH + w) * LL + l] =
                (amv < -10.f) ? -CUDART_INF_F : (acc + skb[w]) * 0.125f;
        }
    }
}

// ---------------- 10: softmax over l, in place. grid (B*H), 512 threads ----------------
__global__ void k_softmax_w() {
    const int t = threadIdx.x;
    const int bh = blockIdx.x;
    __shared__ float red[LL];
    const float v = g_w[(size_t)bh * LL + t];
    red[t] = v;
    __syncthreads();
    for (int s = 256; s > 0; s >>= 1) {
        if (t < s) red[t] = fmaxf(red[t], red[t + s]);
        __syncthreads();
    }
    const float m = red[0];
    __syncthreads();
    const float e = __expf(v - m);
    red[t] = e;
    __syncthreads();
    for (int s = 256; s > 0; s >>= 1) {
        if (t < s) red[t] += red[t + s];
        __syncthreads();
    }
    g_w[(size_t)bh * LL + t] = e / red[0];
}

// ---------------- 11: hv[b,h,d] += sum_{l in chunk} w[b,h,l]*hidden[b,l,d] ----------
// grid (6 dchunks, 8 lchunks, B), 128 threads, chunk of 64 l's, 12 accumulators
__global__ void k_hv(const float* __restrict__ hidden) {
    const int t  = threadIdx.x;
    const int dc = blockIdx.x;
    const int lc = blockIdx.y;
    const int b  = blockIdx.z;
    __shared__ float sw[HH * 64];    // 3 KB
    for (int i = t; i < HH * 64; i += 128) {
        const int h = i >> 6, l = i & 63;
        sw[i] = g_w[((size_t)b * HH + h) * LL + lc * 64 + l];
    }
    __syncthreads();

    float acc[HH];
#pragma unroll
    for (int h = 0; h < HH; h++) acc[h] = 0.f;

    const float* hp = hidden + ((size_t)b * LL + lc * 64) * DD + dc * 128 + t;
#pragma unroll 4
    for (int l = 0; l < 64; l++) {
        const float hval = hp[(size_t)l * DD];
#pragma unroll
        for (int h = 0; h < HH; h++) acc[h] += sw[h * 64 + l] * hval;
    }
#pragma unroll
    for (int h = 0; h < HH; h++)
        atomicAdd(&g_hv[((size_t)b * HH + h) * DD + dc * 128 + t], acc[h]);
}

// ---------------- 12: ctx[b, h*64+d] = hv[b,h]·Wv[:,h*64+d] + bv ----------------
// grid (H, B), 64 threads
__global__ void k_ctx(const float* __restrict__ Wv, const float* __restrict__ bv) {
    const int t = threadIdx.x;   // = d within head
    const int h = blockIdx.x;
    const int b = blockIdx.y;
    __shared__ float sh[DD];
    for (int i = t; i < DD; i += 64) sh[i] = g_hv[((size_t)b * HH + h) * DD + i];
    __syncthreads();
    float acc = bv[h * HD + t];
#pragma unroll 4
    for (int j = 0; j < DD; j++) acc += sh[j] * Wv[(size_t)j * DD + h * HD + t];
    g_ctx[b * DD + h * HD + t] = acc;
}

// ---------------- 13: new_token = ctx @ Wo + bo, write row 255 ----------------
// grid (6, B), 128 threads
__global__ void k_newtok(const float* __restrict__ Wo, const float* __restrict__ bo,
                         float* __restrict__ out) {
    const int t  = threadIdx.x;
    const int dc = blockIdx.x;
    const int b  = blockIdx.y;
    __shared__ float sc[DD];
    for (int i = t; i < DD; i += 128) sc[i] = g_ctx[b * DD + i];
    __syncthreads();
    const int d = dc * 128 + t;
    float acc = bo[d];
#pragma unroll 4
    for (int j = 0; j < DD; j++) acc += sc[j] * Wo[(size_t)j * DD + d];
    out[((size_t)b * KOUT + KSEL) * DD + d] = acc;
}

// ---------------- 14: gather preserved rows + mask ----------------
// grid (KSEL, B), 192 threads (float4)
__global__ void k_gather(const float* __restrict__ hidden, const float* __restrict__ am,
                         float* __restrict__ out) {
    const int t = threadIdx.x;
    const int k = blockIdx.x;
    const int b = blockIdx.y;
    const int idx = g_idx[b * KSEL + k];
    const float4* src = (const float4*)(hidden + ((size_t)b * LL + idx) * DD);
    float4* dst = (float4*)(out + ((size_t)b * KOUT + k) * DD);
    dst[t] = src[t];
    if (t == 0) {
        out[OUT_MASK_OFF + (size_t)b * KOUT + k] = am[b * LL + idx];
    }
}

// ---------------- launcher ----------------
extern "C" void kernel_launch(void* const* d_in, const int* in_sizes, int n_in,
                              void* d_out, int out_size) {
    const float* hidden = (const float*)d_in[0];
    const float* am     = (const float*)d_in[1];
    const float* scores = (const float*)d_in[2];
    const float* Wq     = (const float*)d_in[3];
    const float* bq     = (const float*)d_in[4];
    const float* Wk     = (const float*)d_in[5];
    const float* bk     = (const float*)d_in[6];
    const float* Wv     = (const float*)d_in[7];
    const float* bv     = (const float*)d_in[8];
    const float* Wo     = (const float*)d_in[9];
    const float* bo     = (const float*)d_in[10];
    float* out = (float*)d_out;

    k_zero<<<(BB * HH * DD + 511) / 512, 512>>>();                 // our #1
    k_tome_init<<<(BB * KOUT + 255) / 256, 256>>>(out);            // our #2
    k_att<<<BB, LL>>>(am);                                         // our #3
    k_reduce_scores<<<BB * HH * 2, 128>>>(scores, am);             // our #4 (profiled)
    k_topk<<<BB, LL>>>(am);                                        // our #5
    {
        dim3 g(6, 8, BB);
        k_sentence<<<g, 128>>>(hidden);
    }
    {
        dim3 g(6, BB);
        k_qproj<<<g, 128>>>(Wq, bq);
    }
    {
        dim3 g(HH, BB);
        k_wkeff<<<g, 256>>>(Wk, bk);
    }
    {
        dim3 g(32, BB);
        k_logits<<<g, 384>>>(hidden, am);
    }
    k_softmax_w<<<BB * HH, LL>>>();
    {
        dim3 g(6, 8, BB);
        k_hv<<<g, 128>>>(hidden);
    }
    {
        dim3 g(HH, BB);
        k_ctx<<<g, 64>>>(Wv, bv);
    }
    {
        dim3 g(6, BB);
        k_newtok<<<g, 128>>>(Wo, bo, out);
    }
    {
        dim3 g(KSEL, BB);
        k_gather<<<g, 192>>>(hidden, am, out);
    }
}

// round 6
// speedup vs baseline: 2.8690x; 2.3798x over previous
#include <cuda_runtime.h>
#include <math_constants.h>
#include <cstdint>

#define BB 32
#define HH 12
#define LL 512
#define DD 768
#define HD 64
#define KSEL 255
#define KOUT 256

#define OUT_MASK_OFF ((size_t)BB * KOUT * DD)
#define OUT_TOME_OFF (OUT_MASK_OFF + (size_t)BB * KOUT)

// ---------------- scratch ----------------
__device__ float g_imp[BB * LL];
__device__ float g_att[BB * LL];
__device__ int   g_idx[BB * KSEL];
__device__ float g_sent[BB * DD];
__device__ float g_kbias[BB * HH];
__device__ float g_wke[BB * HH * DD];
__device__ float g_w[BB * HH * LL];
__device__ float g_hv[BB * HH * DD];
__device__ float g_ctx[BB * DD];

// ---------------- 1: prologue — zero accumulators, tome/mask constants, att softmax
// grid 64 x 512. Blocks 0..31 also compute att = softmax(am[b]).
__global__ void k_prologue(const float* __restrict__ am, float* __restrict__ out) {
    const int t = threadIdx.x;
    const int b = blockIdx.x;
    const int gid = b * 512 + t;
    const int nthr = 64 * 512;

    for (int i = gid; i < BB * LL; i += nthr) g_imp[i] = 0.f;
    for (int i = gid; i < BB * DD; i += nthr) g_sent[i] = 0.f;
    for (int i = gid; i < BB * HH * DD; i += nthr) g_hv[i] = 0.f;
    for (int i = gid; i < BB * KOUT; i += nthr) out[OUT_TOME_OFF + i] = 1.f;
    if (gid < BB) out[OUT_MASK_OFF + (size_t)gid * KOUT + KSEL] = 0.f;

    if (b < BB) {
        __shared__ float red[LL];
        const float amv = am[b * LL + t];
        red[t] = amv;
        __syncthreads();
        for (int s = 256; s > 0; s >>= 1) {
            if (t < s) red[t] = fmaxf(red[t], red[t + s]);
            __syncthreads();
        }
        const float m = red[0];
        __syncthreads();
        const float e = __expf(amv - m);
        red[t] = e;
        __syncthreads();
        for (int s = 256; s > 0; s >>= 1) {
            if (t < s) red[t] += red[t + s];
            __syncthreads();
        }
        g_att[b * LL + t] = e / red[0];
    }
}

// ---------------- 2: sentences[b,d] += sum_{l chunk} att*hidden  (grid 6,8,B x128)
__global__ void k_sentence(const float* __restrict__ hidden) {
    const int t  = threadIdx.x;
    const int dc = blockIdx.x;
    const int lc = blockIdx.y;
    const int b  = blockIdx.z;
    __shared__ float s_att[64];
    if (t < 64) s_att[t] = g_att[b * LL + lc * 64 + t];
    __syncthreads();

    const float* hp = hidden + ((size_t)b * LL + lc * 64) * DD + dc * 128 + t;
    float acc = 0.f;
#pragma unroll 16
    for (int l = 0; l < 64; l++) acc += s_att[l] * hp[(size_t)l * DD];
    atomicAdd(&g_sent[b * DD + dc * 128 + t], acc);
}

// ---------------- 3: fused q-projection + effective-key  (grid (H,B) x512)
// phase1: qh[d] = sum_j sent[j]*Wq[j, h*64+d] + bq   (8 j-groups x 64 d, smem reduce)
// phase2: wke[b,h,j] = dot64(Wk[j, h-slice], qh); kbias = dot64(qh, bk_h)
__global__ void k_qk(const float* __restrict__ Wq, const float* __restrict__ bq,
                     const float* __restrict__ Wk, const float* __restrict__ bk) {
    const int t = threadIdx.x;
    const int h = blockIdx.x;
    const int b = blockIdx.y;
    __shared__ float s_sent[DD];
    __shared__ float s_part[8][HD];
    __shared__ float s_qh[HD];

    for (int i = t; i < DD; i += 512) s_sent[i] = g_sent[b * DD + i];
    __syncthreads();

    const int jg = t >> 6;
    const int d  = t & 63;
    {
        float acc = 0.f;
        const float* wp = Wq + h * HD + d;
#pragma unroll 8
        for (int j = jg * 96; j < jg * 96 + 96; j++)
            acc += s_sent[j] * wp[(size_t)j * DD];
        s_part[jg][d] = acc;
    }
    __syncthreads();
    if (t < HD) {
        float q = bq[h * HD + t];
#pragma unroll
        for (int g = 0; g < 8; g++) q += s_part[g][t];
        s_qh[t] = q;
    }
    __syncthreads();

    // kbias (warp 0)
    if (t < 32) {
        float kb = s_qh[t] * bk[h * HD + t] + s_qh[t + 32] * bk[h * HD + t + 32];
#pragma unroll
        for (int off = 16; off; off >>= 1) kb += __shfl_down_sync(0xffffffffu, kb, off);
        if (t == 0) g_kbias[b * HH + h] = kb;
    }

    // phase2: 16 warps x 48 j's, lanes split d (coalesced row reads)
    const int w = t >> 5, lane = t & 31;
    const float qa = s_qh[lane], qb = s_qh[lane + 32];
    for (int j = w * 48; j < w * 48 + 48; j++) {
        const float* wp = Wk + (size_t)j * DD + h * HD;
        float a = wp[lane] * qa + wp[lane + 32] * qb;
#pragma unroll
        for (int off = 16; off; off >>= 1) a += __shfl_down_sync(0xffffffffu, a, off);
        if (lane == 0) g_wke[((size_t)b * HH + h) * DD + j] = a;
    }
}

// ---------------- 4: logits (PROFILED)  grid (32,B) x384
__global__ void k_logits(const float* __restrict__ hidden, const float* __restrict__ am) {
    const int t = threadIdx.x;
    const int b = blockIdx.y;
    __shared__ float swk[HH * DD];   // 36 KB
    __shared__ float skb[HH];
    for (int i = t; i < HH * DD; i += 384) swk[i] = g_wke[(size_t)b * HH * DD + i];
    if (t < HH) skb[t] = g_kbias[b * HH + t];
    __syncthreads();

    const int w = t >> 5, lane = t & 31;
    for (int li = 0; li < 16; li++) {
        const int l = blockIdx.x * 16 + li;
        const float* hp = hidden + ((size_t)b * LL + l) * DD;
        float acc = 0.f;
#pragma unroll
        for (int i = lane; i < DD; i += 32) acc += hp[i] * swk[w * DD + i];
#pragma unroll
        for (int off = 16; off; off >>= 1) acc += __shfl_down_sync(0xffffffffu, acc, off);
        if (lane == 0) {
            const float amv = am[b * LL + l];
            g_w[((size_t)b * HH + w) * LL + l] =
                (amv < -10.f) ? -CUDART_INF_F : (acc + skb[w]) * 0.125f;
        }
    }
}

// ---------------- 5: softmax over l, in place. grid (B*H) x512
__global__ void k_softmax_w() {
    const int t = threadIdx.x;
    const int bh = blockIdx.x;
    __shared__ float red[LL];
    const float v = g_w[(size_t)bh * LL + t];
    red[t] = v;
    __syncthreads();
    for (int s = 256; s > 0; s >>= 1) {
        if (t < s) red[t] = fmaxf(red[t], red[t + s]);
        __syncthreads();
    }
    const float m = red[0];
    __syncthreads();
    const float e = __expf(v - m);
    red[t] = e;
    __syncthreads();
    for (int s = 256; s > 0; s >>= 1) {
        if (t < s) red[t] += red[t + s];
        __syncthreads();
    }
    g_w[(size_t)bh * LL + t] = e / red[0];
}

// ---------------- 6: hv[b,h,d] += sum_{l chunk} w*hidden  (grid 6,8,B x128)
__global__ void k_hv(const float* __restrict__ hidden) {
    const int t  = threadIdx.x;
    const int dc = blockIdx.x;
    const int lc = blockIdx.y;
    const int b  = blockIdx.z;
    __shared__ float sw[HH * 64];
    for (int i = t; i < HH * 64; i += 128) {
        const int h = i >> 6, l = i & 63;
        sw[i] = g_w[((size_t)b * HH + h) * LL + lc * 64 + l];
    }
    __syncthreads();

    float acc[HH];
#pragma unroll
    for (int h = 0; h < HH; h++) acc[h] = 0.f;

    const float* hp = hidden + ((size_t)b * LL + lc * 64) * DD + dc * 128 + t;
#pragma unroll 4
    for (int l = 0; l < 64; l++) {
        const float hval = hp[(size_t)l * DD];
#pragma unroll
        for (int h = 0; h < HH; h++) acc[h] += sw[h * 64 + l] * hval;
    }
#pragma unroll
    for (int h = 0; h < HH; h++)
        atomicAdd(&g_hv[((size_t)b * HH + h) * DD + dc * 128 + t], acc[h]);
}

// ---------------- 7: ctx[b, h*64+d] = hv[b,h]·Wv[:, h-slice] + bv  (grid (H,B) x512)
__global__ void k_ctx(const float* __restrict__ Wv, const float* __restrict__ bv) {
    const int t = threadIdx.x;
    const int h = blockIdx.x;
    const int b = blockIdx.y;
    __shared__ float sh[DD];
    __shared__ float s_part[8][HD];
    for (int i = t; i < DD; i += 512) sh[i] = g_hv[((size_t)b * HH + h) * DD + i];
    __syncthreads();

    const int jg = t >> 6;
    const int d  = t & 63;
    float acc = 0.f;
    const float* wp = Wv + h * HD + d;
#pragma unroll 8
    for (int j = jg * 96; j < jg * 96 + 96; j++)
        acc += sh[j] * wp[(size_t)j * DD];
    s_part[jg][d] = acc;
    __syncthreads();
    if (t < HD) {
        float c = bv[h * HD + t];
#pragma unroll
        for (int g = 0; g < 8; g++) c += s_part[g][t];
        g_ctx[b * DD + h * HD + t] = c;
    }
}

// ---------------- 8: new_token = ctx @ Wo + bo  (grid (6,B) x512)
__global__ void k_newtok(const float* __restrict__ Wo, const float* __restrict__ bo,
                         float* __restrict__ out) {
    const int t  = threadIdx.x;
    const int dc = blockIdx.x;
    const int b  = blockIdx.y;
    __shared__ float sc[DD];
    __shared__ float s_part[4][128];
    for (int i = t; i < DD; i += 512) sc[i] = g_ctx[b * DD + i];
    __syncthreads();

    const int jg = t >> 7;
    const int d  = t & 127;
    float acc = 0.f;
    const float* wp = Wo + dc * 128 + d;
#pragma unroll 8
    for (int j = jg * 192; j < jg * 192 + 192; j++)
        acc += sc[j] * wp[(size_t)j * DD];
    s_part[jg][d] = acc;
    __syncthreads();
    if (t < 128) {
        float o = bo[dc * 128 + t] + s_part[0][t] + s_part[1][t] + s_part[2][t] + s_part[3][t];
        out[((size_t)b * KOUT + KSEL) * DD + dc * 128 + t] = o;
    }
}

// ---------------- 9: column-sum of scores (402 MB) grid B*H*4 x128
__global__ void k_reduce_scores(const float* __restrict__ scores,
                                const float* __restrict__ am) {
    const int t   = threadIdx.x;
    const int blk = blockIdx.x;
    const int qc  = blk & 3;
    const int bh  = blk >> 2;
    const int b   = bh / HH;

    __shared__ float s_af[128];
    const int q0 = qc * 128;
    {
        float amv = am[b * LL + q0 + t];
        s_af[t] = (amv > -10.f) ? 1.f : 0.f;
    }
    __syncthreads();

    const float4* base = (const float4*)(scores + ((size_t)bh * LL + q0) * LL) + t;

    float4 a0 = make_float4(0.f, 0.f, 0.f, 0.f);
    float4 a1 = make_float4(0.f, 0.f, 0.f, 0.f);
#pragma unroll 8
    for (int q = 0; q < 64; q++) {
        const float af0 = s_af[q];
        const float af1 = s_af[q + 64];
        float4 v0 = __ldcs(base + (size_t)q * (LL / 4));
        float4 v1 = __ldcs(base + (size_t)(q + 64) * (LL / 4));
        a0.x += af0 * v0.x; a0.y += af0 * v0.y;
        a0.z += af0 * v0.z; a0.w += af0 * v0.w;
        a1.x += af1 * v1.x; a1.y += af1 * v1.y;
        a1.z += af1 * v1.z; a1.w += af1 * v1.w;
    }
    float* dst = &g_imp[b * LL + t * 4];
    atomicAdd(dst + 0, a0.x + a1.x);
    atomicAdd(dst + 1, a0.y + a1.y);
    atomicAdd(dst + 2, a0.z + a1.z);
    atomicAdd(dst + 3, a0.w + a1.w);
}

// ---------------- 10: top-K (exact stable rank + scan)  grid B x512
__global__ void k_topk(const float* __restrict__ am) {
    const int t = threadIdx.x;
    const int b = blockIdx.x;

    __shared__ float sv[LL];
    __shared__ int   ssc[LL];

    const float amv = am[b * LL + t];
    const float afl = (amv > -10.f) ? 1.f : 0.f;
    float v = g_imp[b * LL + t] * afl * (1.0f / (HH * LL));
    if (t == 0) v = CUDART_INF_F;
    sv[t] = v;
    __syncthreads();

    int rank = 0;
#pragma unroll 8
    for (int j = 0; j < LL; j++) {
        float vj = sv[j];
        rank += (vj > v) || (vj == v && j < t);
    }
    const int sel = (rank < KSEL) ? 1 : 0;

    ssc[t] = sel;
    __syncthreads();
    for (int off = 1; off < LL; off <<= 1) {
        int y = (t >= off) ? ssc[t - off] : 0;
        __syncthreads();
        ssc[t] += y;
        __syncthreads();
    }
    if (sel) g_idx[b * KSEL + (ssc[t] - 1)] = t;
}

// ---------------- 11: gather preserved rows + mask  grid (KSEL,B) x192
__global__ void k_gather(const float* __restrict__ hidden, const float* __restrict__ am,
                         float* __restrict__ out) {
    const int t = threadIdx.x;
    const int k = blockIdx.x;
    const int b = blockIdx.y;
    const int idx = g_idx[b * KSEL + k];
    const float4* src = (const float4*)(hidden + ((size_t)b * LL + idx) * DD);
    float4* dst = (float4*)(out + ((size_t)b * KOUT + k) * DD);
    dst[t] = src[t];
    if (t == 0) {
        out[OUT_MASK_OFF + (size_t)b * KOUT + k] = am[b * LL + idx];
    }
}

// ---------------- launcher ----------------
extern "C" void kernel_launch(void* const* d_in, const int* in_sizes, int n_in,
                              void* d_out, int out_size) {
    const float* hidden = (const float*)d_in[0];
    const float* am     = (const float*)d_in[1];
    const float* scores = (const float*)d_in[2];
    const float* Wq     = (const float*)d_in[3];
    const float* bq     = (const float*)d_in[4];
    const float* Wk     = (const float*)d_in[5];
    const float* bk     = (const float*)d_in[6];
    const float* Wv     = (const float*)d_in[7];
    const float* bv     = (const float*)d_in[8];
    const float* Wo     = (const float*)d_in[9];
    const float* bo     = (const float*)d_in[10];
    float* out = (float*)d_out;

    k_prologue<<<64, 512>>>(am, out);                           // #1
    {
        dim3 g(6, 8, BB);
        k_sentence<<<g, 128>>>(hidden);                         // #2
    }
    {
        dim3 g(HH, BB);
        k_qk<<<g, 512>>>(Wq, bq, Wk, bk);                       // #3
    }
    {
        dim3 g(32, BB);
        k_logits<<<g, 384>>>(hidden, am);                       // #4 (profiled)
    }
    k_softmax_w<<<BB * HH, 512>>>();                            // #5
    {
        dim3 g(6, 8, BB);
        k_hv<<<g, 128>>>(hidden);                               // #6
    }
    {
        dim3 g(HH, BB);
        k_ctx<<<g, 512>>>(Wv, bv);                              // #7
    }
    {
        dim3 g(6, BB);
        k_newtok<<<g, 512>>>(Wo, bo, out);                      // #8
    }
    k_reduce_scores<<<BB * HH * 4, 128>>>(scores, am);          // #9
    k_topk<<<BB, 512>>>(am);                                    // #10
    {
        dim3 g(KSEL, BB);
        k_gather<<<g, 192>>>(hidden, am, out);                  // #11
    }
}

// round 7
// speedup vs baseline: 3.5551x; 1.2392x over previous
#include <cuda_runtime.h>
#include <math_constants.h>
#include <cstdint>

#define BB 32
#define HH 12
#define LL 512
#define DD 768
#define HD 64
#define KSEL 255
#define KOUT 256

#define OUT_MASK_OFF ((size_t)BB * KOUT * DD)
#define OUT_TOME_OFF (OUT_MASK_OFF + (size_t)BB * KOUT)

// ---------------- scratch ----------------
__device__ float g_imp[BB * LL];
__device__ float g_att[BB * LL];
__device__ int   g_idx[BB * KSEL];
__device__ float g_sent[BB * DD];
__device__ float g_kbias[BB * HH];
__device__ float g_wke[BB * HH * DD];
__device__ float g_w[BB * HH * LL];
__device__ float g_hv[BB * HH * DD];
__device__ float g_ctx[BB * DD];

// ---------------- 1: prologue — zero accumulators, tome/mask constants, att softmax
__global__ void k_prologue(const float* __restrict__ am, float* __restrict__ out) {
    const int t = threadIdx.x;
    const int b = blockIdx.x;
    const int gid = b * 512 + t;
    const int nthr = 64 * 512;

    for (int i = gid; i < BB * LL; i += nthr) g_imp[i] = 0.f;
    for (int i = gid; i < BB * DD; i += nthr) g_sent[i] = 0.f;
    for (int i = gid; i < BB * HH * DD; i += nthr) g_hv[i] = 0.f;
    for (int i = gid; i < BB * KOUT; i += nthr) out[OUT_TOME_OFF + i] = 1.f;
    if (gid < BB) out[OUT_MASK_OFF + (size_t)gid * KOUT + KSEL] = 0.f;

    if (b < BB) {
        __shared__ float red[LL];
        const float amv = am[b * LL + t];
        red[t] = amv;
        __syncthreads();
        for (int s = 256; s > 0; s >>= 1) {
            if (t < s) red[t] = fmaxf(red[t], red[t + s]);
            __syncthreads();
        }
        const float m = red[0];
        __syncthreads();
        const float e = __expf(amv - m);
        red[t] = e;
        __syncthreads();
        for (int s = 256; s > 0; s >>= 1) {
            if (t < s) red[t] += red[t + s];
            __syncthreads();
        }
        g_att[b * LL + t] = e / red[0];
    }
}

// ---------------- 2: sentences[b,d] += sum_{l chunk} att*hidden  (grid 6,8,B x128)
__global__ void k_sentence(const float* __restrict__ hidden) {
    const int t  = threadIdx.x;
    const int dc = blockIdx.x;
    const int lc = blockIdx.y;
    const int b  = blockIdx.z;
    __shared__ float s_att[64];
    if (t < 64) s_att[t] = g_att[b * LL + lc * 64 + t];
    __syncthreads();

    const float* hp = hidden + ((size_t)b * LL + lc * 64) * DD + dc * 128 + t;
    float acc = 0.f;
#pragma unroll 16
    for (int l = 0; l < 64; l++) acc += s_att[l] * hp[(size_t)l * DD];
    atomicAdd(&g_sent[b * DD + dc * 128 + t], acc);
}

// ---------------- 3: fused q-projection + effective-key  (grid (H,B) x512)
__global__ void k_qk(const float* __restrict__ Wq, const float* __restrict__ bq,
                     const float* __restrict__ Wk, const float* __restrict__ bk) {
    const int t = threadIdx.x;
    const int h = blockIdx.x;
    const int b = blockIdx.y;
    __shared__ float s_sent[DD];
    __shared__ float s_part[8][HD];
    __shared__ float s_qh[HD];

    for (int i = t; i < DD; i += 512) s_sent[i] = g_sent[b * DD + i];
    __syncthreads();

    const int jg = t >> 6;
    const int d  = t & 63;
    {
        float acc = 0.f;
        const float* wp = Wq + h * HD + d;
#pragma unroll 8
        for (int j = jg * 96; j < jg * 96 + 96; j++)
            acc += s_sent[j] * wp[(size_t)j * DD];
        s_part[jg][d] = acc;
    }
    __syncthreads();
    if (t < HD) {
        float q = bq[h * HD + t];
#pragma unroll
        for (int g = 0; g < 8; g++) q += s_part[g][t];
        s_qh[t] = q;
    }
    __syncthreads();

    if (t < 32) {
        float kb = s_qh[t] * bk[h * HD + t] + s_qh[t + 32] * bk[h * HD + t + 32];
#pragma unroll
        for (int off = 16; off; off >>= 1) kb += __shfl_down_sync(0xffffffffu, kb, off);
        if (t == 0) g_kbias[b * HH + h] = kb;
    }

    const int w = t >> 5, lane = t & 31;
    const float qa = s_qh[lane], qb = s_qh[lane + 32];
    for (int j = w * 48; j < w * 48 + 48; j++) {
        const float* wp = Wk + (size_t)j * DD + h * HD;
        float a = wp[lane] * qa + wp[lane + 32] * qb;
#pragma unroll
        for (int off = 16; off; off >>= 1) a += __shfl_down_sync(0xffffffffu, a, off);
        if (lane == 0) g_wke[((size_t)b * HH + h) * DD + j] = a;
    }
}

// ---------------- 4: logits (PROFILED)  grid (32,B) x384
// Stage 16x768 hidden tile in smem once; wke row in 24 regs/lane; batch shfl reduces.
__global__ void k_logits(const float* __restrict__ hidden, const float* __restrict__ am) {
    const int t = threadIdx.x;
    const int b = blockIdx.y;
    const int l0 = blockIdx.x * 16;
    __shared__ float s_h[16 * DD];   // 48 KB
    __shared__ float skb[HH];

    // stage hidden tile (contiguous 48 KB, float4 coalesced)
    {
        const float4* src = (const float4*)(hidden + ((size_t)b * LL + l0) * DD);
        float4* dst = (float4*)s_h;
#pragma unroll
        for (int i = t; i < 16 * DD / 4; i += 384) dst[i] = src[i];
    }
    if (t < HH) skb[t] = g_kbias[b * HH + t];

    const int h = t >> 5, lane = t & 31;
    float wk[24];
    {
        const float* wkp = g_wke + ((size_t)b * HH + h) * DD + lane;
#pragma unroll
        for (int j = 0; j < 24; j++) wk[j] = wkp[32 * j];
    }
    __syncthreads();

    float acc[16];
#pragma unroll
    for (int li = 0; li < 16; li++) {
        const float* hp = s_h + li * DD + lane;
        float a = 0.f;
#pragma unroll
        for (int j = 0; j < 24; j++) a += hp[32 * j] * wk[j];
        acc[li] = a;
    }
#pragma unroll
    for (int li = 0; li < 16; li++) {
        float a = acc[li];
#pragma unroll
        for (int off = 16; off; off >>= 1) a += __shfl_down_sync(0xffffffffu, a, off);
        if (lane == 0) {
            const int l = l0 + li;
            const float amv = am[b * LL + l];
            g_w[((size_t)b * HH + h) * LL + l] =
                (amv < -10.f) ? -CUDART_INF_F : (a + skb[h]) * 0.125f;
        }
    }
}

// ---------------- 5: softmax over l, in place. grid (B*H) x512
__global__ void k_softmax_w() {
    const int t = threadIdx.x;
    const int bh = blockIdx.x;
    __shared__ float red[LL];
    const float v = g_w[(size_t)bh * LL + t];
    red[t] = v;
    __syncthreads();
    for (int s = 256; s > 0; s >>= 1) {
        if (t < s) red[t] = fmaxf(red[t], red[t + s]);
        __syncthreads();
    }
    const float m = red[0];
    __syncthreads();
    const float e = __expf(v - m);
    red[t] = e;
    __syncthreads();
    for (int s = 256; s > 0; s >>= 1) {
        if (t < s) red[t] += red[t + s];
        __syncthreads();
    }
    g_w[(size_t)bh * LL + t] = e / red[0];
}

// ---------------- 6: hv[b,h,d] += sum_{l chunk} w*hidden  (grid 6,8,B x128)
__global__ void k_hv(const float* __restrict__ hidden) {
    const int t  = threadIdx.x;
    const int dc = blockIdx.x;
    const int lc = blockIdx.y;
    const int b  = blockIdx.z;
    __shared__ float sw[HH * 64];
    for (int i = t; i < HH * 64; i += 128) {
        const int h = i >> 6, l = i & 63;
        sw[i] = g_w[((size_t)b * HH + h) * LL + lc * 64 + l];
    }
    __syncthreads();

    float acc[HH];
#pragma unroll
    for (int h = 0; h < HH; h++) acc[h] = 0.f;

    const float* hp = hidden + ((size_t)b * LL + lc * 64) * DD + dc * 128 + t;
#pragma unroll 4
    for (int l = 0; l < 64; l++) {
        const float hval = hp[(size_t)l * DD];
#pragma unroll
        for (int h = 0; h < HH; h++) acc[h] += sw[h * 64 + l] * hval;
    }
#pragma unroll
    for (int h = 0; h < HH; h++)
        atomicAdd(&g_hv[((size_t)b * HH + h) * DD + dc * 128 + t], acc[h]);
}

// ---------------- 7: ctx[b, h*64+d] = hv[b,h]·Wv[:, h-slice] + bv  (grid (H,B) x512)
__global__ void k_ctx(const float* __restrict__ Wv, const float* __restrict__ bv) {
    const int t = threadIdx.x;
    const int h = blockIdx.x;
    const int b = blockIdx.y;
    __shared__ float sh[DD];
    __shared__ float s_part[8][HD];
    for (int i = t; i < DD; i += 512) sh[i] = g_hv[((size_t)b * HH + h) * DD + i];
    __syncthreads();

    const int jg = t >> 6;
    const int d  = t & 63;
    float acc = 0.f;
    const float* wp = Wv + h * HD + d;
#pragma unroll 8
    for (int j = jg * 96; j < jg * 96 + 96; j++)
        acc += sh[j] * wp[(size_t)j * DD];
    s_part[jg][d] = acc;
    __syncthreads();
    if (t < HD) {
        float c = bv[h * HD + t];
#pragma unroll
        for (int g = 0; g < 8; g++) c += s_part[g][t];
        g_ctx[b * DD + h * HD + t] = c;
    }
}

// ---------------- 8: new_token = ctx @ Wo + bo  (grid (6,B) x512)
__global__ void k_newtok(const float* __restrict__ Wo, const float* __restrict__ bo,
                         float* __restrict__ out) {
    const int t  = threadIdx.x;
    const int dc = blockIdx.x;
    const int b  = blockIdx.y;
    __shared__ float sc[DD];
    __shared__ float s_part[4][128];
    for (int i = t; i < DD; i += 512) sc[i] = g_ctx[b * DD + i];
    __syncthreads();

    const int jg = t >> 7;
    const int d  = t & 127;
    float acc = 0.f;
    const float* wp = Wo + dc * 128 + d;
#pragma unroll 8
    for (int j = jg * 192; j < jg * 192 + 192; j++)
        acc += sc[j] * wp[(size_t)j * DD];
    s_part[jg][d] = acc;
    __syncthreads();
    if (t < 128) {
        float o = bo[dc * 128 + t] + s_part[0][t] + s_part[1][t] + s_part[2][t] + s_part[3][t];
        out[((size_t)b * KOUT + KSEL) * DD + dc * 128 + t] = o;
    }
}

// ---------------- 9: column-sum of scores (402 MB) grid B*H*4 x256
// 256 threads: q-half split (t>>7), col = t&127; 8-deep __ldcs MLP per thread.
__global__ void k_reduce_scores(const float* __restrict__ scores,
                                const float* __restrict__ am) {
    const int t   = threadIdx.x;
    const int blk = blockIdx.x;
    const int qc  = blk & 3;
    const int bh  = blk >> 2;
    const int b   = bh / HH;

    __shared__ float s_af[128];
    const int q0 = qc * 128;
    if (t < 128) {
        float amv = am[b * LL + q0 + t];
        s_af[t] = (amv > -10.f) ? 1.f : 0.f;
    }
    __syncthreads();

    const int tq  = t >> 7;          // 0/1: q-half of 64
    const int col = t & 127;
    const float4* base =
        (const float4*)(scores + ((size_t)bh * LL + q0 + tq * 64) * LL) + col;
    const float* af = s_af + tq * 64;

    float4 a0 = make_float4(0.f, 0.f, 0.f, 0.f);
#pragma unroll 8
    for (int q = 0; q < 64; q++) {
        const float f = af[q];
        float4 v = __ldcs(base + (size_t)q * (LL / 4));
        a0.x += f * v.x; a0.y += f * v.y;
        a0.z += f * v.z; a0.w += f * v.w;
    }
    float* dst = &g_imp[b * LL + col * 4];
    atomicAdd(dst + 0, a0.x);
    atomicAdd(dst + 1, a0.y);
    atomicAdd(dst + 2, a0.z);
    atomicAdd(dst + 3, a0.w);
}

// ---------------- 10: top-K (exact stable rank + scan)  grid B x512
__global__ void k_topk(const float* __restrict__ am) {
    const int t = threadIdx.x;
    const int b = blockIdx.x;

    __shared__ float sv[LL];
    __shared__ int   ssc[LL];

    const float amv = am[b * LL + t];
    const float afl = (amv > -10.f) ? 1.f : 0.f;
    float v = g_imp[b * LL + t] * afl * (1.0f / (HH * LL));
    if (t == 0) v = CUDART_INF_F;
    sv[t] = v;
    __syncthreads();

    int rank = 0;
#pragma unroll 8
    for (int j = 0; j < LL; j++) {
        float vj = sv[j];
        rank += (vj > v) || (vj == v && j < t);
    }
    const int sel = (rank < KSEL) ? 1 : 0;

    ssc[t] = sel;
    __syncthreads();
    for (int off = 1; off < LL; off <<= 1) {
        int y = (t >= off) ? ssc[t - off] : 0;
        __syncthreads();
        ssc[t] += y;
        __syncthreads();
    }
    if (sel) g_idx[b * KSEL + (ssc[t] - 1)] = t;
}

// ---------------- 11: gather preserved rows + mask  grid (KSEL,B) x192
__global__ void k_gather(const float* __restrict__ hidden, const float* __restrict__ am,
                         float* __restrict__ out) {
    const int t = threadIdx.x;
    const int k = blockIdx.x;
    const int b = blockIdx.y;
    const int idx = g_idx[b * KSEL + k];
    const float4* src = (const float4*)(hidden + ((size_t)b * LL + idx) * DD);
    float4* dst = (float4*)(out + ((size_t)b * KOUT + k) * DD);
    dst[t] = src[t];
    if (t == 0) {
        out[OUT_MASK_OFF + (size_t)b * KOUT + k] = am[b * LL + idx];
    }
}

// ---------------- launcher ----------------
extern "C" void kernel_launch(void* const* d_in, const int* in_sizes, int n_in,
                              void* d_out, int out_size) {
    const float* hidden = (const float*)d_in[0];
    const float* am     = (const float*)d_in[1];
    const float* scores = (const float*)d_in[2];
    const float* Wq     = (const float*)d_in[3];
    const float* bq     = (const float*)d_in[4];
    const float* Wk     = (const float*)d_in[5];
    const float* bk     = (const float*)d_in[6];
    const float* Wv     = (const float*)d_in[7];
    const float* bv     = (const float*)d_in[8];
    const float* Wo     = (const float*)d_in[9];
    const float* bo     = (const float*)d_in[10];
    float* out = (float*)d_out;

    k_prologue<<<64, 512>>>(am, out);                           // #1
    {
        dim3 g(6, 8, BB);
        k_sentence<<<g, 128>>>(hidden);                         // #2
    }
    {
        dim3 g(HH, BB);
        k_qk<<<g, 512>>>(Wq, bq, Wk, bk);                       // #3
    }
    {
        dim3 g(32, BB);
        k_logits<<<g, 384>>>(hidden, am);                       // #4 (profiled)
    }
    k_softmax_w<<<BB * HH, 512>>>();                            // #5
    {
        dim3 g(6, 8, BB);
        k_hv<<<g, 128>>>(hidden);                               // #6
    }
    {
        dim3 g(HH, BB);
        k_ctx<<<g, 512>>>(Wv, bv);                              // #7
    }
    {
        dim3 g(6, BB);
        k_newtok<<<g, 512>>>(Wo, bo, out);                      // #8
    }
    k_reduce_scores<<<BB * HH * 4, 256>>>(scores, am);          // #9
    k_topk<<<BB, 512>>>(am);                                    // #10
    {
        dim3 g(KSEL, BB);
        k_gather<<<g, 192>>>(hidden, am, out);                  // #11
    }
}